// round 13
// baseline (speedup 1.0000x reference)
#include <cuda_runtime.h>
#include <cuda_bf16.h>
#include <cstdint>

// Problem dims
#define Bc 8
#define Tc 2048
#define Hc 64
#define Mc 32
#define Sc 20
#define Ec 3
#define INc 32
#define BTc (Bc*Tc)          // 16384
#define EBc (Ec*Bc)          // 24
#define EPSc 1e-8f
#define LOG2E 1.4426950408889634f

// attention tiling
#define NK 64                // keys per chunk
#define NCH (Tc/NK)          // 32 chunks
#define QTILES (Tc/128)      // 16

// Scratch (static __device__ arrays: allocation-free per harness rules)
__device__ __align__(16) __nv_bfloat16 g_Qb[EBc*Tc*64];   // [eb][t][qh 0-31 | ql 32-63], log2e-scaled
__device__ __align__(16) __nv_bfloat16 g_Kb[EBc*Tc*64];   // [eb][t][kh 0-31 | kl 32-63]
__device__ __align__(16) __nv_bfloat16 g_Vt[EBc*NCH*64*64]; // per chunk: V^T [m: vh 0-31|vl 32-63][key 0-63]
__device__ float g_mem[BTc*Mc];                            // memories [B*T, 32]

// ---------- helpers ----------
__device__ __forceinline__ float ex2(float x) {
    float r; asm("ex2.approx.f32 %0, %1;" : "=f"(r) : "f"(x)); return r;
}
__device__ __forceinline__ uint32_t smem_u32(const void* p) {
    return (uint32_t)__cvta_generic_to_shared(p);
}
__device__ __forceinline__ void cp16(uint32_t dst, const void* src) {
    asm volatile("cp.async.cg.shared.global [%0], [%1], 16;" :: "r"(dst), "l"(src));
}
__device__ __forceinline__ void cp_commit() { asm volatile("cp.async.commit_group;"); }
template <int N> __device__ __forceinline__ void cp_wait() {
    asm volatile("cp.async.wait_group %0;" :: "n"(N));
}
// bf16x2 pack: result = {hi16 = cvt(a), lo16 = cvt(b)}
__device__ __forceinline__ uint32_t cvt2(float hi, float lo) {
    uint32_t r;
    asm("cvt.rn.bf16x2.f32 %0, %1, %2;" : "=r"(r) : "f"(hi), "f"(lo));
    return r;
}
// HMMA m16n8k16 row.col f32.bf16.bf16.f32
__device__ __forceinline__ void mma16816(float* c, const uint32_t* a, uint32_t b0, uint32_t b1) {
    asm volatile("mma.sync.aligned.m16n8k16.row.col.f32.bf16.bf16.f32 "
        "{%0,%1,%2,%3}, {%4,%5,%6,%7}, {%8,%9}, {%0,%1,%2,%3};"
        : "+f"(c[0]), "+f"(c[1]), "+f"(c[2]), "+f"(c[3])
        : "r"(a[0]), "r"(a[1]), "r"(a[2]), "r"(a[3]), "r"(b0), "r"(b1));
}

// ============================================================================
// Kernel 1: memories = softmax(x@IQ @ mem^T) @ mem     [B*T, 32]
// 2 threads per row (each owns 16 m-cols) -> ~60 regs, no spills.
// ============================================================================
__global__ __launch_bounds__(256)
void k_mem(const float* __restrict__ x, const float* __restrict__ memory,
           const float* __restrict__ iq) {
    __shared__ float IQs[INc*Mc];
    __shared__ float MEMs[Sc*Mc];
    int tid = threadIdx.x;
    for (int i = tid; i < INc*Mc; i += 256) IQs[i] = iq[i];
    for (int i = tid; i < Sc*Mc; i += 256) MEMs[i] = memory[i];
    __syncthreads();

    int row = blockIdx.x * 128 + (tid >> 1);
    int half = tid & 1;
    int c0 = half * 16;
    const float4* x4 = (const float4*)(x + (size_t)row * INc);

    float q[16];
    #pragma unroll
    for (int j = 0; j < 16; j++) q[j] = 0.f;
    #pragma unroll
    for (int i4 = 0; i4 < 8; i4++) {
        float4 v = x4[i4];
        int i = i4 * 4;
        #pragma unroll
        for (int j = 0; j < 16; j++) q[j] = fmaf(v.x, IQs[(i+0)*Mc + c0 + j], q[j]);
        #pragma unroll
        for (int j = 0; j < 16; j++) q[j] = fmaf(v.y, IQs[(i+1)*Mc + c0 + j], q[j]);
        #pragma unroll
        for (int j = 0; j < 16; j++) q[j] = fmaf(v.z, IQs[(i+2)*Mc + c0 + j], q[j]);
        #pragma unroll
        for (int j = 0; j < 16; j++) q[j] = fmaf(v.w, IQs[(i+3)*Mc + c0 + j], q[j]);
    }
    float lg[Sc];
    #pragma unroll
    for (int s = 0; s < Sc; s++) {
        float acc = 0.f;
        #pragma unroll
        for (int j = 0; j < 16; j++) acc = fmaf(q[j], MEMs[s*Mc + c0 + j], acc);
        acc += __shfl_xor_sync(0xffffffffu, acc, 1);
        lg[s] = acc;
    }
    float mx = lg[0];
    #pragma unroll
    for (int s = 1; s < Sc; s++) mx = fmaxf(mx, lg[s]);
    float sum = 0.f;
    #pragma unroll
    for (int s = 0; s < Sc; s++) { lg[s] = ex2((lg[s] - mx) * LOG2E); sum += lg[s]; }
    float inv = 1.0f / sum;
    float* op = g_mem + (size_t)row*Mc + c0;
    #pragma unroll
    for (int j = 0; j < 16; j++) {
        float acc = 0.f;
        #pragma unroll
        for (int s = 0; s < Sc; s++) acc = fmaf(lg[s], MEMs[s*Mc + c0 + j], acc);
        op[j] = acc * inv;
    }
}

// ============================================================================
// Kernel 2: QKV projections -> bf16 hi/lo, dense MMA-ready tiles.
// ============================================================================
__global__ __launch_bounds__(256)
void k_qkv(const float* __restrict__ hidden, const float* __restrict__ Wq,
           const float* __restrict__ Wk, const float* __restrict__ Wv) {
    __shared__ float Ws[3*Hc*Mc];
    int e = blockIdx.y;
    int tid = threadIdx.x;
    {
        const float4* wq4 = (const float4*)(Wq + (size_t)e*Hc*Mc);
        const float4* wk4 = (const float4*)(Wk + (size_t)e*Hc*Mc);
        const float4* wv4 = (const float4*)(Wv + (size_t)e*Hc*Mc);
        float4* s0 = (float4*)Ws;
        float4* s1 = (float4*)(Ws + Hc*Mc);
        float4* s2 = (float4*)(Ws + 2*Hc*Mc);
        for (int i = tid; i < Hc*Mc/4; i += 256) { s0[i] = wq4[i]; s1[i] = wk4[i]; s2[i] = wv4[i]; }
    }
    __syncthreads();

    int warp = tid >> 5, lane = tid & 31;
    int rbase = blockIdx.x * 256 + warp * 32;
    unsigned short vh_p = 0, vl_p = 0;
    for (int i = 0; i < 32; ++i) {
        int row = rbase + i;
        size_t hoff = ((size_t)e*BTc + row) * Hc;
        float2 h2 = ((const float2*)(hidden + hoff))[lane];
        float qa = 0.f, ka = 0.f, va = 0.f;
        #pragma unroll
        for (int h = 0; h < Hc; ++h) {
            float hv = __shfl_sync(0xffffffffu, (h & 1) ? h2.y : h2.x, h >> 1);
            qa = fmaf(hv, Ws[h*Mc + lane], qa);
            ka = fmaf(hv, Ws[Hc*Mc + h*Mc + lane], ka);
            va = fmaf(hv, Ws[2*Hc*Mc + h*Mc + lane], va);
        }
        qa *= LOG2E;
        __nv_bfloat16 qh = __float2bfloat16(qa);
        __nv_bfloat16 qlo = __float2bfloat16(qa - __bfloat162float(qh));
        __nv_bfloat16 kh = __float2bfloat16(ka);
        __nv_bfloat16 klo = __float2bfloat16(ka - __bfloat162float(kh));
        __nv_bfloat16 vh = __float2bfloat16(va);
        __nv_bfloat16 vlo = __float2bfloat16(va - __bfloat162float(vh));

        int bb = row >> 11, tt = row & 2047;
        int eb = e * Bc + bb;
        size_t qko = ((size_t)eb*Tc + tt) * 64;
        g_Qb[qko + lane]      = qh;
        g_Qb[qko + lane + 32] = qlo;
        g_Kb[qko + lane]      = kh;
        g_Kb[qko + lane + 32] = klo;
        // V^T tile: [m 0-63][key 0-63], pair-packed 4B stores every 2 keys
        if (i & 1) {
            int tile = eb*NCH + (tt >> 6);
            int rk = tt & 63;
            __nv_bfloat16* Vt = g_Vt + (size_t)tile * 4096;
            uint32_t phv = ((uint32_t)__bfloat16_as_ushort(vh)  << 16) | vh_p;
            uint32_t plv = ((uint32_t)__bfloat16_as_ushort(vlo) << 16) | vl_p;
            *(uint32_t*)(Vt + lane*64 + (rk-1))        = phv;
            *(uint32_t*)(Vt + (lane+32)*64 + (rk-1))   = plv;
        } else {
            vh_p = __bfloat16_as_ushort(vh); vl_p = __bfloat16_as_ushort(vlo);
        }
    }
}

// ============================================================================
// Kernel 3: HMMA flash attention + fused cosine epilogue.
// CTA = 128 queries (8 warps x 16q), all 2048 keys in 32 chunks of 64.
// bf16 hi/lo emulation: QK = QhKh+QhKl+QlKh; PV = PhVh+PlVh+PhVl.
// Cosine is scale-invariant => no softmax denominator needed.
// ============================================================================
__global__ __launch_bounds__(256)
void k_attn(float* __restrict__ out) {
    // padded rows: 64 cols bf16 = 32 words + 4 pad = 36 words (144B) -> conflict-free
    __shared__ __align__(16) uint32_t sK[2][64*36];
    __shared__ __align__(16) uint32_t sV[2][64*36];

    int tid = threadIdx.x, warp = tid >> 5, lane = tid & 31;
    int qi = lane >> 2, t4 = lane & 3;
    int qtile = blockIdx.x, b = blockIdx.y, e = blockIdx.z;
    int eb = e * Bc + b;

    const char* Kg = (const char*)g_Kb + (size_t)(eb*Tc) * 128;
    const char* Vg = (const char*)g_Vt + (size_t)(eb*NCH) * 8192;

    // ---- load Q fragments (warp owns 16 query rows; held in regs whole kernel) ----
    // aQ[f], f: 0=Qh ks0, 1=Qh ks1, 2=Ql ks0, 3=Ql ks1 ; each 4 regs
    uint32_t aQ[4][4];
    {
        const char* Qg = (const char*)g_Qb + ((size_t)eb*Tc + qtile*128) * 128;
        int r = warp*16 + qi;
        #pragma unroll
        for (int f = 0; f < 4; ++f) {
            int cb = (f >> 1)*32 + (f & 1)*16 + 2*t4;  // col base (bf16 units)
            aQ[f][0] = *(const uint32_t*)(Qg + (size_t)r*128     + cb*2);
            aQ[f][1] = *(const uint32_t*)(Qg + (size_t)(r+8)*128 + cb*2);
            aQ[f][2] = *(const uint32_t*)(Qg + (size_t)r*128     + cb*2 + 16);
            aQ[f][3] = *(const uint32_t*)(Qg + (size_t)(r+8)*128 + cb*2 + 16);
        }
    }

    // ---- prologue: stage chunk 0 (512 x 16B segs each for K and V) ----
    {
        uint32_t dK = smem_u32(&sK[0][0]), dV = smem_u32(&sV[0][0]);
        #pragma unroll
        for (int i = 0; i < 2; ++i) {
            int seg = tid + i*256;
            uint32_t doff = (seg >> 3)*144 + (seg & 7)*16;
            cp16(dK + doff, Kg + seg*16);
            cp16(dV + doff, Vg + seg*16);
        }
        cp_commit();
    }

    float oc[4][4];
    #pragma unroll
    for (int nt = 0; nt < 4; ++nt)
        #pragma unroll
        for (int j = 0; j < 4; ++j) oc[nt][j] = 0.f;
    float mrow0 = -1e30f, mrow1 = -1e30f;

    for (int c = 0; c < NCH; ++c) {
        int buf = c & 1;
        if (c + 1 < NCH) {
            uint32_t dK = smem_u32(&sK[buf^1][0]), dV = smem_u32(&sV[buf^1][0]);
            const char* kp = Kg + (size_t)(c+1)*8192;
            const char* vp = Vg + (size_t)(c+1)*8192;
            #pragma unroll
            for (int i = 0; i < 2; ++i) {
                int seg = tid + i*256;
                uint32_t doff = (seg >> 3)*144 + (seg & 7)*16;
                cp16(dK + doff, kp + seg*16);
                cp16(dV + doff, vp + seg*16);
            }
            cp_commit();
            cp_wait<1>();
        } else {
            cp_wait<0>();
        }
        __syncthreads();

        const uint32_t* Kb = sK[buf];
        const uint32_t* Vb = sV[buf];

        // ---- S = Qh.Kh + Qh.Kl + Ql.Kh  (fp32 frags) ----
        float s[8][4];
        #pragma unroll
        for (int nt = 0; nt < 8; ++nt) {
            uint32_t base = (uint32_t)(nt*8 + qi)*36 + t4;
            uint32_t bh0a = Kb[base],    bh0b = Kb[base+4];
            uint32_t bh1a = Kb[base+8],  bh1b = Kb[base+12];
            uint32_t bl0a = Kb[base+16], bl0b = Kb[base+20];
            uint32_t bl1a = Kb[base+24], bl1b = Kb[base+28];
            float* cc = s[nt];
            cc[0]=0.f; cc[1]=0.f; cc[2]=0.f; cc[3]=0.f;
            mma16816(cc, aQ[0], bh0a, bh0b);
            mma16816(cc, aQ[1], bh1a, bh1b);
            mma16816(cc, aQ[0], bl0a, bl0b);
            mma16816(cc, aQ[1], bl1a, bl1b);
            mma16816(cc, aQ[2], bh0a, bh0b);
            mma16816(cc, aQ[3], bh1a, bh1b);
        }

        // ---- online max update (quad = 4 lanes share a row) ----
        float c0 = -1e30f, c1 = -1e30f;
        #pragma unroll
        for (int nt = 0; nt < 8; ++nt) {
            c0 = fmaxf(c0, fmaxf(s[nt][0], s[nt][1]));
            c1 = fmaxf(c1, fmaxf(s[nt][2], s[nt][3]));
        }
        c0 = fmaxf(c0, __shfl_xor_sync(0xffffffffu, c0, 1));
        c0 = fmaxf(c0, __shfl_xor_sync(0xffffffffu, c0, 2));
        c1 = fmaxf(c1, __shfl_xor_sync(0xffffffffu, c1, 1));
        c1 = fmaxf(c1, __shfl_xor_sync(0xffffffffu, c1, 2));
        float mn0 = fmaxf(mrow0, c0), mn1 = fmaxf(mrow1, c1);
        float sc0 = ex2(mrow0 - mn0), sc1 = ex2(mrow1 - mn1);
        mrow0 = mn0; mrow1 = mn1;
        #pragma unroll
        for (int nt = 0; nt < 4; ++nt) {
            oc[nt][0] *= sc0; oc[nt][1] *= sc0;
            oc[nt][2] *= sc1; oc[nt][3] *= sc1;
        }

        // ---- P (bf16 hi/lo A-frags straight from S frags) + PV ----
        #pragma unroll
        for (int ks = 0; ks < 4; ++ks) {
            float* sa = s[2*ks];
            float* sb = s[2*ks+1];
            float p00 = ex2(sa[0]-mn0), p01 = ex2(sa[1]-mn0);
            float p10 = ex2(sa[2]-mn1), p11 = ex2(sa[3]-mn1);
            float p20 = ex2(sb[0]-mn0), p21 = ex2(sb[1]-mn0);
            float p30 = ex2(sb[2]-mn1), p31 = ex2(sb[3]-mn1);
            uint32_t h0 = cvt2(p01, p00), h1 = cvt2(p11, p10);
            uint32_t h2 = cvt2(p21, p20), h3 = cvt2(p31, p30);
            uint32_t aph[4] = {h0, h1, h2, h3};
            uint32_t apl[4];
            apl[0] = cvt2(p01 - __uint_as_float(h0 & 0xffff0000u),
                          p00 - __uint_as_float(h0 << 16));
            apl[1] = cvt2(p11 - __uint_as_float(h1 & 0xffff0000u),
                          p10 - __uint_as_float(h1 << 16));
            apl[2] = cvt2(p21 - __uint_as_float(h2 & 0xffff0000u),
                          p20 - __uint_as_float(h2 << 16));
            apl[3] = cvt2(p31 - __uint_as_float(h3 & 0xffff0000u),
                          p30 - __uint_as_float(h3 << 16));
            #pragma unroll
            for (int nt = 0; nt < 4; ++nt) {
                uint32_t base = (uint32_t)(nt*8 + qi)*36 + ks*8 + t4;
                uint32_t bh0 = Vb[base],          bh1 = Vb[base+4];
                uint32_t bl0 = Vb[base + 32*36],  bl1 = Vb[base + 32*36 + 4];
                mma16816(oc[nt], aph, bh0, bh1);
                mma16816(oc[nt], apl, bh0, bh1);
                mma16816(oc[nt], aph, bl0, bl1);
            }
        }
        __syncthreads();
    }

    // ---- cosine epilogue (scale-invariant: no softmax denominator) ----
    {
        int t_row = qtile*128 + warp*16 + qi;
        int bt0 = b*Tc + t_row;
        int bt1 = bt0 + 8;
        float d0 = 0.f, n0 = 0.f, g0 = 0.f;
        float d1 = 0.f, n1 = 0.f, g1 = 0.f;
        #pragma unroll
        for (int nt = 0; nt < 4; ++nt) {
            int col = nt*8 + 2*t4;
            float2 m0 = *(const float2*)(g_mem + (size_t)bt0*Mc + col);
            float2 m1 = *(const float2*)(g_mem + (size_t)bt1*Mc + col);
            float o00 = oc[nt][0], o01 = oc[nt][1];
            float o10 = oc[nt][2], o11 = oc[nt][3];
            d0 += m0.x*o00 + m0.y*o01;  n0 += o00*o00 + o01*o01;  g0 += m0.x*m0.x + m0.y*m0.y;
            d1 += m1.x*o10 + m1.y*o11;  n1 += o10*o10 + o11*o11;  g1 += m1.x*m1.x + m1.y*m1.y;
        }
        #pragma unroll
        for (int w = 1; w <= 2; w <<= 1) {
            d0 += __shfl_xor_sync(0xffffffffu, d0, w);
            n0 += __shfl_xor_sync(0xffffffffu, n0, w);
            g0 += __shfl_xor_sync(0xffffffffu, g0, w);
            d1 += __shfl_xor_sync(0xffffffffu, d1, w);
            n1 += __shfl_xor_sync(0xffffffffu, n1, w);
            g1 += __shfl_xor_sync(0xffffffffu, g1, w);
        }
        if (t4 == 0) {
            float cv0 = d0 / (fmaxf(sqrtf(g0), EPSc) * fmaxf(sqrtf(n0), EPSc));
            float cv1 = d1 / (fmaxf(sqrtf(g1), EPSc) * fmaxf(sqrtf(n1), EPSc));
            out[(size_t)bt0*Ec + e] = cv0;
            out[(size_t)bt1*Ec + e] = cv1;
        }
    }
}

// ============================================================================
extern "C" void kernel_launch(void* const* d_in, const int* in_sizes, int n_in,
                              void* d_out, int out_size) {
    (void)in_sizes; (void)n_in; (void)out_size;
    const float* x      = (const float*)d_in[0];
    const float* hidden = (const float*)d_in[1];
    const float* memory = (const float*)d_in[2];
    const float* Wq     = (const float*)d_in[3];
    const float* Wk     = (const float*)d_in[4];
    const float* Wv     = (const float*)d_in[5];
    const float* iq     = (const float*)d_in[6];
    float* out = (float*)d_out;

    k_mem<<<BTc/128, 256>>>(x, memory, iq);
    k_qkv<<<dim3(BTc/256, Ec), 256>>>(hidden, Wq, Wk, Wv);
    k_attn<<<dim3(QTILES, Bc, Ec), 256>>>(out);
}

// round 14
// speedup vs baseline: 1.0728x; 1.0728x over previous
#include <cuda_runtime.h>
#include <cuda_bf16.h>
#include <cstdint>

// Problem dims
#define Bc 8
#define Tc 2048
#define Hc 64
#define Mc 32
#define Sc 20
#define Ec 3
#define INc 32
#define BTc (Bc*Tc)          // 16384
#define EBc (Ec*Bc)          // 24
#define EBT (EBc*Tc)         // 49152
#define EPSc 1e-8f
#define LOG2E 1.4426950408889634f

// attention tiling
#define NK 64                // keys per chunk
#define NCH (Tc/NK)          // 32 chunks total
#define KQS 2                // key splits
#define NCHH (NCH/KQS)       // 16 chunks per CTA
#define QTILES (Tc/128)      // 16

// Scratch (static __device__ arrays: allocation-free per harness rules)
__device__ __align__(16) __nv_bfloat16 g_Qb[EBc*Tc*64];   // [eb][t][qh 0-31 | ql 32-63], log2e-scaled
__device__ __align__(16) __nv_bfloat16 g_Kb[EBc*Tc*64];   // [eb][t][kh 0-31 | kl 32-63]
__device__ __align__(16) __nv_bfloat16 g_Vt[EBc*NCH*64*64]; // per chunk: V^T [m: vh 0-31|vl 32-63][key 0-63]
__device__ float g_mem[BTc*Mc];                            // memories [B*T, 32]
__device__ float g_pO[KQS*EBT*Mc];                         // unnormalized partial O
__device__ float g_pm[KQS*EBT];                            // partial max (log2 domain)

// ---------- helpers ----------
__device__ __forceinline__ float ex2(float x) {
    float r; asm("ex2.approx.f32 %0, %1;" : "=f"(r) : "f"(x)); return r;
}
__device__ __forceinline__ uint32_t smem_u32(const void* p) {
    return (uint32_t)__cvta_generic_to_shared(p);
}
__device__ __forceinline__ void cp16(uint32_t dst, const void* src) {
    asm volatile("cp.async.cg.shared.global [%0], [%1], 16;" :: "r"(dst), "l"(src));
}
__device__ __forceinline__ void cp_commit() { asm volatile("cp.async.commit_group;"); }
template <int N> __device__ __forceinline__ void cp_wait() {
    asm volatile("cp.async.wait_group %0;" :: "n"(N));
}
// bf16x2 pack: result = {hi16 = cvt(a), lo16 = cvt(b)}
__device__ __forceinline__ uint32_t cvt2(float hi, float lo) {
    uint32_t r;
    asm("cvt.rn.bf16x2.f32 %0, %1, %2;" : "=r"(r) : "f"(hi), "f"(lo));
    return r;
}
// HMMA m16n8k16 row.col f32.bf16.bf16.f32
__device__ __forceinline__ void mma16816(float* c, const uint32_t* a, uint32_t b0, uint32_t b1) {
    asm volatile("mma.sync.aligned.m16n8k16.row.col.f32.bf16.bf16.f32 "
        "{%0,%1,%2,%3}, {%4,%5,%6,%7}, {%8,%9}, {%0,%1,%2,%3};"
        : "+f"(c[0]), "+f"(c[1]), "+f"(c[2]), "+f"(c[3])
        : "r"(a[0]), "r"(a[1]), "r"(a[2]), "r"(a[3]), "r"(b0), "r"(b1));
}

// ============================================================================
// Kernel 1: memories = softmax(x@IQ @ mem^T) @ mem     [B*T, 32]
// 4 threads per row (each owns 8 m-cols) -> ~45 regs, no spills.
// ============================================================================
__global__ __launch_bounds__(256)
void k_mem(const float* __restrict__ x, const float* __restrict__ memory,
           const float* __restrict__ iq) {
    __shared__ float IQs[INc*Mc];
    __shared__ float MEMs[Sc*Mc];
    int tid = threadIdx.x;
    for (int i = tid; i < INc*Mc; i += 256) IQs[i] = iq[i];
    for (int i = tid; i < Sc*Mc; i += 256) MEMs[i] = memory[i];
    __syncthreads();

    int row = blockIdx.x * 64 + (tid >> 2);
    int c0 = (tid & 3) * 8;
    const float4* x4 = (const float4*)(x + (size_t)row * INc);

    float q[8];
    #pragma unroll
    for (int j = 0; j < 8; j++) q[j] = 0.f;
    #pragma unroll
    for (int i4 = 0; i4 < 8; i4++) {
        float4 v = x4[i4];
        int i = i4 * 4;
        #pragma unroll
        for (int j = 0; j < 8; j++) q[j] = fmaf(v.x, IQs[(i+0)*Mc + c0 + j], q[j]);
        #pragma unroll
        for (int j = 0; j < 8; j++) q[j] = fmaf(v.y, IQs[(i+1)*Mc + c0 + j], q[j]);
        #pragma unroll
        for (int j = 0; j < 8; j++) q[j] = fmaf(v.z, IQs[(i+2)*Mc + c0 + j], q[j]);
        #pragma unroll
        for (int j = 0; j < 8; j++) q[j] = fmaf(v.w, IQs[(i+3)*Mc + c0 + j], q[j]);
    }
    float lg[Sc];
    #pragma unroll
    for (int s = 0; s < Sc; s++) {
        float acc = 0.f;
        #pragma unroll
        for (int j = 0; j < 8; j++) acc = fmaf(q[j], MEMs[s*Mc + c0 + j], acc);
        acc += __shfl_xor_sync(0xffffffffu, acc, 1);
        acc += __shfl_xor_sync(0xffffffffu, acc, 2);
        lg[s] = acc;
    }
    float mx = lg[0];
    #pragma unroll
    for (int s = 1; s < Sc; s++) mx = fmaxf(mx, lg[s]);
    float sum = 0.f;
    #pragma unroll
    for (int s = 0; s < Sc; s++) { lg[s] = ex2((lg[s] - mx) * LOG2E); sum += lg[s]; }
    float inv = 1.0f / sum;
    float* op = g_mem + (size_t)row*Mc + c0;
    #pragma unroll
    for (int j = 0; j < 8; j++) {
        float acc = 0.f;
        #pragma unroll
        for (int s = 0; s < Sc; s++) acc = fmaf(lg[s], MEMs[s*Mc + c0 + j], acc);
        op[j] = acc * inv;
    }
}

// ============================================================================
// Kernel 2: QKV projections -> bf16 hi/lo, dense MMA-ready tiles.
// ============================================================================
__global__ __launch_bounds__(256)
void k_qkv(const float* __restrict__ hidden, const float* __restrict__ Wq,
           const float* __restrict__ Wk, const float* __restrict__ Wv) {
    __shared__ float Ws[3*Hc*Mc];
    int e = blockIdx.y;
    int tid = threadIdx.x;
    {
        const float4* wq4 = (const float4*)(Wq + (size_t)e*Hc*Mc);
        const float4* wk4 = (const float4*)(Wk + (size_t)e*Hc*Mc);
        const float4* wv4 = (const float4*)(Wv + (size_t)e*Hc*Mc);
        float4* s0 = (float4*)Ws;
        float4* s1 = (float4*)(Ws + Hc*Mc);
        float4* s2 = (float4*)(Ws + 2*Hc*Mc);
        for (int i = tid; i < Hc*Mc/4; i += 256) { s0[i] = wq4[i]; s1[i] = wk4[i]; s2[i] = wv4[i]; }
    }
    __syncthreads();

    int warp = tid >> 5, lane = tid & 31;
    int rbase = blockIdx.x * 256 + warp * 32;
    unsigned short vh_p = 0, vl_p = 0;
    for (int i = 0; i < 32; ++i) {
        int row = rbase + i;
        size_t hoff = ((size_t)e*BTc + row) * Hc;
        float2 h2 = ((const float2*)(hidden + hoff))[lane];
        float qa = 0.f, ka = 0.f, va = 0.f;
        #pragma unroll
        for (int h = 0; h < Hc; ++h) {
            float hv = __shfl_sync(0xffffffffu, (h & 1) ? h2.y : h2.x, h >> 1);
            qa = fmaf(hv, Ws[h*Mc + lane], qa);
            ka = fmaf(hv, Ws[Hc*Mc + h*Mc + lane], ka);
            va = fmaf(hv, Ws[2*Hc*Mc + h*Mc + lane], va);
        }
        qa *= LOG2E;
        __nv_bfloat16 qh = __float2bfloat16(qa);
        __nv_bfloat16 qlo = __float2bfloat16(qa - __bfloat162float(qh));
        __nv_bfloat16 kh = __float2bfloat16(ka);
        __nv_bfloat16 klo = __float2bfloat16(ka - __bfloat162float(kh));
        __nv_bfloat16 vh = __float2bfloat16(va);
        __nv_bfloat16 vlo = __float2bfloat16(va - __bfloat162float(vh));

        int bb = row >> 11, tt = row & 2047;
        int eb = e * Bc + bb;
        size_t qko = ((size_t)eb*Tc + tt) * 64;
        g_Qb[qko + lane]      = qh;
        g_Qb[qko + lane + 32] = qlo;
        g_Kb[qko + lane]      = kh;
        g_Kb[qko + lane + 32] = klo;
        // V^T tile: [m 0-63][key 0-63], pair-packed 4B stores every 2 keys
        if (i & 1) {
            int tile = eb*NCH + (tt >> 6);
            int rk = tt & 63;
            __nv_bfloat16* Vt = g_Vt + (size_t)tile * 4096;
            uint32_t phv = ((uint32_t)__bfloat16_as_ushort(vh)  << 16) | vh_p;
            uint32_t plv = ((uint32_t)__bfloat16_as_ushort(vlo) << 16) | vl_p;
            *(uint32_t*)(Vt + lane*64 + (rk-1))        = phv;
            *(uint32_t*)(Vt + (lane+32)*64 + (rk-1))   = plv;
        } else {
            vh_p = __bfloat16_as_ushort(vh); vl_p = __bfloat16_as_ushort(vlo);
        }
    }
}

// ============================================================================
// Kernel 3: HMMA flash attention, key-split partials.
// CTA = 128 queries (4 warps x 32q) x 1024 keys (16 chunks of 64).
// bf16 hi/lo emulation: QK = QhKh+QhKl+QlKh; PV = PhVh+PlVh+PhVl.
// Cosine scale-invariance => only running max kept, no denominator.
// grid (QTILES*KQS, B, E), block 128.
// ============================================================================
__global__ __launch_bounds__(128)
void k_attn() {
    // padded rows: 64 cols bf16 = 32 words + 4 pad = 36 words (144B) -> conflict-free
    __shared__ __align__(16) uint32_t sK[2][64*36];
    __shared__ __align__(16) uint32_t sV[2][64*36];

    int tid = threadIdx.x, warp = tid >> 5, lane = tid & 31;
    int qi = lane >> 2, t4 = lane & 3;
    int qtile = blockIdx.x >> 1, kh = blockIdx.x & 1;
    int b = blockIdx.y, e = blockIdx.z;
    int eb = e * Bc + b;
    int co = kh * NCHH;   // first chunk of this key half

    const char* Kg = (const char*)g_Kb + (size_t)(eb*Tc) * 128;
    const char* Vg = (const char*)g_Vt + (size_t)(eb*NCH) * 8192;

    // ---- load Q fragments (held in registers whole kernel) ----
    uint32_t aQ[2][4][4];
    {
        const char* Qg = (const char*)g_Qb + ((size_t)eb*Tc + qtile*128) * 128;
        #pragma unroll
        for (int mt = 0; mt < 2; ++mt) {
            int r = warp*32 + mt*16 + qi;
            #pragma unroll
            for (int f = 0; f < 4; ++f) {
                int cb = (f >> 1)*32 + (f & 1)*16 + 2*t4;
                aQ[mt][f][0] = *(const uint32_t*)(Qg + (size_t)r*128     + cb*2);
                aQ[mt][f][1] = *(const uint32_t*)(Qg + (size_t)(r+8)*128 + cb*2);
                aQ[mt][f][2] = *(const uint32_t*)(Qg + (size_t)r*128     + cb*2 + 16);
                aQ[mt][f][3] = *(const uint32_t*)(Qg + (size_t)(r+8)*128 + cb*2 + 16);
            }
        }
    }

    // ---- prologue: stage chunk co ----
    {
        uint32_t dK = smem_u32(&sK[0][0]), dV = smem_u32(&sV[0][0]);
        const char* kp = Kg + (size_t)co*8192;
        const char* vp = Vg + (size_t)co*8192;
        #pragma unroll
        for (int i = 0; i < 4; ++i) {
            int seg = tid + i*128;
            uint32_t doff = (seg >> 3)*144 + (seg & 7)*16;
            cp16(dK + doff, kp + seg*16);
            cp16(dV + doff, vp + seg*16);
        }
        cp_commit();
    }

    float oc[2][4][4];
    #pragma unroll
    for (int mt = 0; mt < 2; ++mt)
        #pragma unroll
        for (int nt = 0; nt < 4; ++nt)
            #pragma unroll
            for (int j = 0; j < 4; ++j) oc[mt][nt][j] = 0.f;
    float mrow[2][2] = {{-1e30f,-1e30f},{-1e30f,-1e30f}};

    for (int c = 0; c < NCHH; ++c) {
        int buf = c & 1;
        if (c + 1 < NCHH) {
            uint32_t dK = smem_u32(&sK[buf^1][0]), dV = smem_u32(&sV[buf^1][0]);
            const char* kp = Kg + (size_t)(co+c+1)*8192;
            const char* vp = Vg + (size_t)(co+c+1)*8192;
            #pragma unroll
            for (int i = 0; i < 4; ++i) {
                int seg = tid + i*128;
                uint32_t doff = (seg >> 3)*144 + (seg & 7)*16;
                cp16(dK + doff, kp + seg*16);
                cp16(dV + doff, vp + seg*16);
            }
            cp_commit();
            cp_wait<1>();
        } else {
            cp_wait<0>();
        }
        __syncthreads();

        const uint32_t* Kb = sK[buf];
        const uint32_t* Vb = sV[buf];

        // ---- S = Qh.Kh + Qh.Kl + Ql.Kh  (fp32 frags) ----
        float s[2][8][4];
        #pragma unroll
        for (int nt = 0; nt < 8; ++nt) {
            uint32_t base = (uint32_t)(nt*8 + qi)*36 + t4;
            uint32_t bh0a = Kb[base],    bh0b = Kb[base+4];
            uint32_t bh1a = Kb[base+8],  bh1b = Kb[base+12];
            uint32_t bl0a = Kb[base+16], bl0b = Kb[base+20];
            uint32_t bl1a = Kb[base+24], bl1b = Kb[base+28];
            #pragma unroll
            for (int mt = 0; mt < 2; ++mt) {
                float* cc = s[mt][nt];
                cc[0]=0.f; cc[1]=0.f; cc[2]=0.f; cc[3]=0.f;
                mma16816(cc, aQ[mt][0], bh0a, bh0b);
                mma16816(cc, aQ[mt][1], bh1a, bh1b);
                mma16816(cc, aQ[mt][0], bl0a, bl0b);
                mma16816(cc, aQ[mt][1], bl1a, bl1b);
                mma16816(cc, aQ[mt][2], bh0a, bh0b);
                mma16816(cc, aQ[mt][3], bh1a, bh1b);
            }
        }

        // ---- online max update ----
        float mn[2][2];
        #pragma unroll
        for (int mt = 0; mt < 2; ++mt) {
            float c0 = -1e30f, c1 = -1e30f;
            #pragma unroll
            for (int nt = 0; nt < 8; ++nt) {
                c0 = fmaxf(c0, fmaxf(s[mt][nt][0], s[mt][nt][1]));
                c1 = fmaxf(c1, fmaxf(s[mt][nt][2], s[mt][nt][3]));
            }
            c0 = fmaxf(c0, __shfl_xor_sync(0xffffffffu, c0, 1));
            c0 = fmaxf(c0, __shfl_xor_sync(0xffffffffu, c0, 2));
            c1 = fmaxf(c1, __shfl_xor_sync(0xffffffffu, c1, 1));
            c1 = fmaxf(c1, __shfl_xor_sync(0xffffffffu, c1, 2));
            mn[mt][0] = fmaxf(mrow[mt][0], c0);
            mn[mt][1] = fmaxf(mrow[mt][1], c1);
            float sc0 = ex2(mrow[mt][0] - mn[mt][0]);
            float sc1 = ex2(mrow[mt][1] - mn[mt][1]);
            mrow[mt][0] = mn[mt][0];
            mrow[mt][1] = mn[mt][1];
            #pragma unroll
            for (int nt = 0; nt < 4; ++nt) {
                oc[mt][nt][0] *= sc0; oc[mt][nt][1] *= sc0;
                oc[mt][nt][2] *= sc1; oc[mt][nt][3] *= sc1;
            }
        }

        // ---- P (bf16 hi/lo A-frags straight from S frags) + PV ----
        #pragma unroll
        for (int ks = 0; ks < 4; ++ks) {
            uint32_t aph[2][4], apl[2][4];
            #pragma unroll
            for (int mt = 0; mt < 2; ++mt) {
                float* sa = s[mt][2*ks];
                float* sb = s[mt][2*ks+1];
                float p00 = ex2(sa[0]-mn[mt][0]), p01 = ex2(sa[1]-mn[mt][0]);
                float p10 = ex2(sa[2]-mn[mt][1]), p11 = ex2(sa[3]-mn[mt][1]);
                float p20 = ex2(sb[0]-mn[mt][0]), p21 = ex2(sb[1]-mn[mt][0]);
                float p30 = ex2(sb[2]-mn[mt][1]), p31 = ex2(sb[3]-mn[mt][1]);
                uint32_t h0 = cvt2(p01, p00), h1 = cvt2(p11, p10);
                uint32_t h2 = cvt2(p21, p20), h3 = cvt2(p31, p30);
                aph[mt][0] = h0; aph[mt][1] = h1; aph[mt][2] = h2; aph[mt][3] = h3;
                apl[mt][0] = cvt2(p01 - __uint_as_float(h0 & 0xffff0000u),
                                  p00 - __uint_as_float(h0 << 16));
                apl[mt][1] = cvt2(p11 - __uint_as_float(h1 & 0xffff0000u),
                                  p10 - __uint_as_float(h1 << 16));
                apl[mt][2] = cvt2(p21 - __uint_as_float(h2 & 0xffff0000u),
                                  p20 - __uint_as_float(h2 << 16));
                apl[mt][3] = cvt2(p31 - __uint_as_float(h3 & 0xffff0000u),
                                  p30 - __uint_as_float(h3 << 16));
            }
            #pragma unroll
            for (int nt = 0; nt < 4; ++nt) {
                uint32_t base = (uint32_t)(nt*8 + qi)*36 + ks*8 + t4;
                uint32_t bh0 = Vb[base],          bh1 = Vb[base+4];
                uint32_t bl0 = Vb[base + 32*36],  bl1 = Vb[base + 32*36 + 4];
                #pragma unroll
                for (int mt = 0; mt < 2; ++mt) {
                    mma16816(oc[mt][nt], aph[mt], bh0, bh1);
                    mma16816(oc[mt][nt], apl[mt], bh0, bh1);
                    mma16816(oc[mt][nt], aph[mt], bl0, bl1);
                }
            }
        }
        __syncthreads();
    }

    // ---- write unnormalized partials (O frags + per-row max) ----
    #pragma unroll
    for (int mt = 0; mt < 2; ++mt) {
        int t_row = qtile*128 + warp*32 + mt*16 + qi;
        size_t r0 = ((size_t)kh*EBT + (size_t)eb*Tc + t_row) * Mc;
        size_t r1 = r0 + 8*Mc;
        #pragma unroll
        for (int nt = 0; nt < 4; ++nt) {
            int col = nt*8 + 2*t4;
            *(float2*)(g_pO + r0 + col) = make_float2(oc[mt][nt][0], oc[mt][nt][1]);
            *(float2*)(g_pO + r1 + col) = make_float2(oc[mt][nt][2], oc[mt][nt][3]);
        }
        if (t4 == 0) {
            g_pm[kh*EBT + eb*Tc + t_row]     = mrow[mt][0];
            g_pm[kh*EBT + eb*Tc + t_row + 8] = mrow[mt][1];
        }
    }
}

// ============================================================================
// Kernel 4: combine key-split partials + cosine epilogue. 1 thread per row.
// ============================================================================
__global__ __launch_bounds__(128)
void k_fin(float* __restrict__ out) {
    int r = blockIdx.x * 128 + threadIdx.x;   // 0 .. EBT-1
    float m0 = g_pm[r], m1 = g_pm[EBT + r];
    float m = fmaxf(m0, m1);
    float w0 = ex2(m0 - m), w1 = ex2(m1 - m);

    int eb = r >> 11, t = r & 2047;
    int e = eb / Bc, b = eb % Bc;
    int bt = b * Tc + t;

    const float4* O0 = (const float4*)(g_pO + (size_t)r * Mc);
    const float4* O1 = (const float4*)(g_pO + (size_t)(EBT + r) * Mc);
    const float4* mem4 = (const float4*)(g_mem + (size_t)bt * Mc);
    float dot = 0.f, no2 = 0.f, nm2 = 0.f;
    #pragma unroll
    for (int i = 0; i < 8; ++i) {
        float4 a = O0[i], bb = O1[i], mm = mem4[i];
        float o0 = w0*a.x + w1*bb.x;
        float o1 = w0*a.y + w1*bb.y;
        float o2 = w0*a.z + w1*bb.z;
        float o3 = w0*a.w + w1*bb.w;
        dot += mm.x*o0 + mm.y*o1 + mm.z*o2 + mm.w*o3;
        nm2 += mm.x*mm.x + mm.y*mm.y + mm.z*mm.z + mm.w*mm.w;
        no2 += o0*o0 + o1*o1 + o2*o2 + o3*o3;
    }
    float cosv = dot / (fmaxf(sqrtf(nm2), EPSc) * fmaxf(sqrtf(no2), EPSc));
    out[(size_t)bt*Ec + e] = cosv;
}

// ============================================================================
extern "C" void kernel_launch(void* const* d_in, const int* in_sizes, int n_in,
                              void* d_out, int out_size) {
    (void)in_sizes; (void)n_in; (void)out_size;
    const float* x      = (const float*)d_in[0];
    const float* hidden = (const float*)d_in[1];
    const float* memory = (const float*)d_in[2];
    const float* Wq     = (const float*)d_in[3];
    const float* Wk     = (const float*)d_in[4];
    const float* Wv     = (const float*)d_in[5];
    const float* iq     = (const float*)d_in[6];
    float* out = (float*)d_out;

    k_mem<<<BTc/64, 256>>>(x, memory, iq);
    k_qkv<<<dim3(BTc/256, Ec), 256>>>(hidden, Wq, Wk, Wv);
    k_attn<<<dim3(QTILES*KQS, Bc, Ec), 128>>>();
    k_fin<<<EBT/128, 128>>>(out);
}

// round 16
// speedup vs baseline: 1.1099x; 1.0346x over previous
#include <cuda_runtime.h>
#include <cuda_bf16.h>
#include <cstdint>

// Problem dims
#define Bc 8
#define Tc 2048
#define Hc 64
#define Mc 32
#define Sc 20
#define Ec 3
#define INc 32
#define BTc (Bc*Tc)          // 16384
#define EBc (Ec*Bc)          // 24
#define EBT (EBc*Tc)         // 49152
#define EPSc 1e-8f
#define LOG2E 1.4426950408889634f

// attention tiling
#define NK 64                // keys per chunk
#define NCH (Tc/NK)          // 32 chunks total
#define KQS 3                // key splits (chunks split 11/11/10)
#define QTILES (Tc/128)      // 16

// Scratch (static __device__ arrays: allocation-free per harness rules)
__device__ __align__(16) __nv_bfloat16 g_Qb[EBc*Tc*64];   // [eb][t][qh 0-31 | ql 32-63], log2e-scaled
__device__ __align__(16) __nv_bfloat16 g_Kb[EBc*Tc*64];   // [eb][t][kh 0-31 | kl 32-63]
__device__ __align__(16) __nv_bfloat16 g_Vt[EBc*NCH*64*64]; // per chunk: V^T [m: vh 0-31|vl 32-63][key 0-63]
__device__ float g_mem[BTc*Mc];                            // memories [B*T, 32]
__device__ float g_pO[KQS*EBT*Mc];                         // unnormalized partial O
__device__ float g_pm[KQS*EBT];                            // partial max (log2 domain)

// ---------- helpers ----------
__device__ __forceinline__ float ex2(float x) {
    float r; asm("ex2.approx.f32 %0, %1;" : "=f"(r) : "f"(x)); return r;
}
__device__ __forceinline__ uint32_t smem_u32(const void* p) {
    return (uint32_t)__cvta_generic_to_shared(p);
}
__device__ __forceinline__ void cp16(uint32_t dst, const void* src) {
    asm volatile("cp.async.cg.shared.global [%0], [%1], 16;" :: "r"(dst), "l"(src));
}
__device__ __forceinline__ void cp_commit() { asm volatile("cp.async.commit_group;"); }
template <int N> __device__ __forceinline__ void cp_wait() {
    asm volatile("cp.async.wait_group %0;" :: "n"(N));
}
// bf16x2 pack: result = {hi16 = cvt(a), lo16 = cvt(b)}
__device__ __forceinline__ uint32_t cvt2(float hi, float lo) {
    uint32_t r;
    asm("cvt.rn.bf16x2.f32 %0, %1, %2;" : "=r"(r) : "f"(hi), "f"(lo));
    return r;
}
// HMMA m16n8k16 row.col f32.bf16.bf16.f32
__device__ __forceinline__ void mma16816(float* c, const uint32_t* a, uint32_t b0, uint32_t b1) {
    asm volatile("mma.sync.aligned.m16n8k16.row.col.f32.bf16.bf16.f32 "
        "{%0,%1,%2,%3}, {%4,%5,%6,%7}, {%8,%9}, {%0,%1,%2,%3};"
        : "+f"(c[0]), "+f"(c[1]), "+f"(c[2]), "+f"(c[3])
        : "r"(a[0]), "r"(a[1]), "r"(a[2]), "r"(a[3]), "r"(b0), "r"(b1));
}

// ============================================================================
// Kernel 1: memories = softmax(x@IQ @ mem^T) @ mem     [B*T, 32]
// 4 threads per row (each owns 8 m-cols).
// ============================================================================
__global__ __launch_bounds__(256)
void k_mem(const float* __restrict__ x, const float* __restrict__ memory,
           const float* __restrict__ iq) {
    __shared__ float IQs[INc*Mc];
    __shared__ float MEMs[Sc*Mc];
    int tid = threadIdx.x;
    for (int i = tid; i < INc*Mc; i += 256) IQs[i] = iq[i];
    for (int i = tid; i < Sc*Mc; i += 256) MEMs[i] = memory[i];
    __syncthreads();

    int row = blockIdx.x * 64 + (tid >> 2);
    int c0 = (tid & 3) * 8;
    const float4* x4 = (const float4*)(x + (size_t)row * INc);

    float q[8];
    #pragma unroll
    for (int j = 0; j < 8; j++) q[j] = 0.f;
    #pragma unroll
    for (int i4 = 0; i4 < 8; i4++) {
        float4 v = x4[i4];
        int i = i4 * 4;
        #pragma unroll
        for (int j = 0; j < 8; j++) q[j] = fmaf(v.x, IQs[(i+0)*Mc + c0 + j], q[j]);
        #pragma unroll
        for (int j = 0; j < 8; j++) q[j] = fmaf(v.y, IQs[(i+1)*Mc + c0 + j], q[j]);
        #pragma unroll
        for (int j = 0; j < 8; j++) q[j] = fmaf(v.z, IQs[(i+2)*Mc + c0 + j], q[j]);
        #pragma unroll
        for (int j = 0; j < 8; j++) q[j] = fmaf(v.w, IQs[(i+3)*Mc + c0 + j], q[j]);
    }
    float lg[Sc];
    #pragma unroll
    for (int s = 0; s < Sc; s++) {
        float acc = 0.f;
        #pragma unroll
        for (int j = 0; j < 8; j++) acc = fmaf(q[j], MEMs[s*Mc + c0 + j], acc);
        acc += __shfl_xor_sync(0xffffffffu, acc, 1);
        acc += __shfl_xor_sync(0xffffffffu, acc, 2);
        lg[s] = acc;
    }
    float mx = lg[0];
    #pragma unroll
    for (int s = 1; s < Sc; s++) mx = fmaxf(mx, lg[s]);
    float sum = 0.f;
    #pragma unroll
    for (int s = 0; s < Sc; s++) { lg[s] = ex2((lg[s] - mx) * LOG2E); sum += lg[s]; }
    float inv = 1.0f / sum;
    float* op = g_mem + (size_t)row*Mc + c0;
    #pragma unroll
    for (int j = 0; j < 8; j++) {
        float acc = 0.f;
        #pragma unroll
        for (int s = 0; s < Sc; s++) acc = fmaf(lg[s], MEMs[s*Mc + c0 + j], acc);
        op[j] = acc * inv;
    }
}

// ============================================================================
// Kernel 2: QKV projections -> bf16 hi/lo, dense MMA-ready tiles.
// ============================================================================
__global__ __launch_bounds__(256)
void k_qkv(const float* __restrict__ hidden, const float* __restrict__ Wq,
           const float* __restrict__ Wk, const float* __restrict__ Wv) {
    __shared__ float Ws[3*Hc*Mc];
    int e = blockIdx.y;
    int tid = threadIdx.x;
    {
        const float4* wq4 = (const float4*)(Wq + (size_t)e*Hc*Mc);
        const float4* wk4 = (const float4*)(Wk + (size_t)e*Hc*Mc);
        const float4* wv4 = (const float4*)(Wv + (size_t)e*Hc*Mc);
        float4* s0 = (float4*)Ws;
        float4* s1 = (float4*)(Ws + Hc*Mc);
        float4* s2 = (float4*)(Ws + 2*Hc*Mc);
        for (int i = tid; i < Hc*Mc/4; i += 256) { s0[i] = wq4[i]; s1[i] = wk4[i]; s2[i] = wv4[i]; }
    }
    __syncthreads();

    int warp = tid >> 5, lane = tid & 31;
    int rbase = blockIdx.x * 256 + warp * 32;
    unsigned short vh_p = 0, vl_p = 0;
    for (int i = 0; i < 32; ++i) {
        int row = rbase + i;
        size_t hoff = ((size_t)e*BTc + row) * Hc;
        float2 h2 = ((const float2*)(hidden + hoff))[lane];
        float qa = 0.f, ka = 0.f, va = 0.f;
        #pragma unroll
        for (int h = 0; h < Hc; ++h) {
            float hv = __shfl_sync(0xffffffffu, (h & 1) ? h2.y : h2.x, h >> 1);
            qa = fmaf(hv, Ws[h*Mc + lane], qa);
            ka = fmaf(hv, Ws[Hc*Mc + h*Mc + lane], ka);
            va = fmaf(hv, Ws[2*Hc*Mc + h*Mc + lane], va);
        }
        qa *= LOG2E;
        __nv_bfloat16 qh = __float2bfloat16(qa);
        __nv_bfloat16 qlo = __float2bfloat16(qa - __bfloat162float(qh));
        __nv_bfloat16 kh = __float2bfloat16(ka);
        __nv_bfloat16 klo = __float2bfloat16(ka - __bfloat162float(kh));
        __nv_bfloat16 vh = __float2bfloat16(va);
        __nv_bfloat16 vlo = __float2bfloat16(va - __bfloat162float(vh));

        int bb = row >> 11, tt = row & 2047;
        int eb = e * Bc + bb;
        size_t qko = ((size_t)eb*Tc + tt) * 64;
        g_Qb[qko + lane]      = qh;
        g_Qb[qko + lane + 32] = qlo;
        g_Kb[qko + lane]      = kh;
        g_Kb[qko + lane + 32] = klo;
        // V^T tile: [m 0-63][key 0-63], pair-packed 4B stores every 2 keys
        if (i & 1) {
            int tile = eb*NCH + (tt >> 6);
            int rk = tt & 63;
            __nv_bfloat16* Vt = g_Vt + (size_t)tile * 4096;
            uint32_t phv = ((uint32_t)__bfloat16_as_ushort(vh)  << 16) | vh_p;
            uint32_t plv = ((uint32_t)__bfloat16_as_ushort(vlo) << 16) | vl_p;
            *(uint32_t*)(Vt + lane*64 + (rk-1))        = phv;
            *(uint32_t*)(Vt + (lane+32)*64 + (rk-1))   = plv;
        } else {
            vh_p = __bfloat16_as_ushort(vh); vl_p = __bfloat16_as_ushort(vlo);
        }
    }
}

// ============================================================================
// Kernel 3: HMMA flash attention, key-split partials.
// CTA = 128 queries (4 warps x 32q) x ~683 keys (11/11/10 chunks of 64).
// bf16 hi/lo emulation: QK = QhKh+QhKl+QlKh; PV = PhVh+PlVh+PhVl.
// Cosine scale-invariance => only running max kept, no denominator.
// __launch_bounds__(128,3): 3 CTAs/SM -> 3 warps/SMSP for latency hiding.
// grid (QTILES*KQS, B, E), block 128.
// ============================================================================
__global__ __launch_bounds__(128, 3)
void k_attn() {
    // padded rows: 64 cols bf16 = 32 words + 4 pad = 36 words (144B) -> conflict-free
    __shared__ __align__(16) uint32_t sK[2][64*36];
    __shared__ __align__(16) uint32_t sV[2][64*36];

    int tid = threadIdx.x, warp = tid >> 5, lane = tid & 31;
    int qi = lane >> 2, t4 = lane & 3;
    int qtile = blockIdx.x / KQS, kh = blockIdx.x % KQS;
    int b = blockIdx.y, e = blockIdx.z;
    int eb = e * Bc + b;
    // chunk ranges: split 32 chunks as 11/11/10
    int co = kh * 11;
    int nch = (kh == 2) ? 10 : 11;

    const char* Kg = (const char*)g_Kb + (size_t)(eb*Tc) * 128;
    const char* Vg = (const char*)g_Vt + (size_t)(eb*NCH) * 8192;

    // ---- load Q fragments (held in registers whole kernel) ----
    uint32_t aQ[2][4][4];
    {
        const char* Qg = (const char*)g_Qb + ((size_t)eb*Tc + qtile*128) * 128;
        #pragma unroll
        for (int mt = 0; mt < 2; ++mt) {
            int r = warp*32 + mt*16 + qi;
            #pragma unroll
            for (int f = 0; f < 4; ++f) {
                int cb = (f >> 1)*32 + (f & 1)*16 + 2*t4;
                aQ[mt][f][0] = *(const uint32_t*)(Qg + (size_t)r*128     + cb*2);
                aQ[mt][f][1] = *(const uint32_t*)(Qg + (size_t)(r+8)*128 + cb*2);
                aQ[mt][f][2] = *(const uint32_t*)(Qg + (size_t)r*128     + cb*2 + 16);
                aQ[mt][f][3] = *(const uint32_t*)(Qg + (size_t)(r+8)*128 + cb*2 + 16);
            }
        }
    }

    // ---- prologue: stage chunk co ----
    {
        uint32_t dK = smem_u32(&sK[0][0]), dV = smem_u32(&sV[0][0]);
        const char* kp = Kg + (size_t)co*8192;
        const char* vp = Vg + (size_t)co*8192;
        #pragma unroll
        for (int i = 0; i < 4; ++i) {
            int seg = tid + i*128;
            uint32_t doff = (seg >> 3)*144 + (seg & 7)*16;
            cp16(dK + doff, kp + seg*16);
            cp16(dV + doff, vp + seg*16);
        }
        cp_commit();
    }

    float oc[2][4][4];
    #pragma unroll
    for (int mt = 0; mt < 2; ++mt)
        #pragma unroll
        for (int nt = 0; nt < 4; ++nt)
            #pragma unroll
            for (int j = 0; j < 4; ++j) oc[mt][nt][j] = 0.f;
    float mrow[2][2] = {{-1e30f,-1e30f},{-1e30f,-1e30f}};

    for (int c = 0; c < nch; ++c) {
        int buf = c & 1;
        if (c + 1 < nch) {
            uint32_t dK = smem_u32(&sK[buf^1][0]), dV = smem_u32(&sV[buf^1][0]);
            const char* kp = Kg + (size_t)(co+c+1)*8192;
            const char* vp = Vg + (size_t)(co+c+1)*8192;
            #pragma unroll
            for (int i = 0; i < 4; ++i) {
                int seg = tid + i*128;
                uint32_t doff = (seg >> 3)*144 + (seg & 7)*16;
                cp16(dK + doff, kp + seg*16);
                cp16(dV + doff, vp + seg*16);
            }
            cp_commit();
            cp_wait<1>();
        } else {
            cp_wait<0>();
        }
        __syncthreads();

        const uint32_t* Kb = sK[buf];
        const uint32_t* Vb = sV[buf];

        // ---- S = Qh.Kh + Qh.Kl + Ql.Kh  (fp32 frags) ----
        float s[2][8][4];
        #pragma unroll
        for (int nt = 0; nt < 8; ++nt) {
            uint32_t base = (uint32_t)(nt*8 + qi)*36 + t4;
            uint32_t bh0a = Kb[base],    bh0b = Kb[base+4];
            uint32_t bh1a = Kb[base+8],  bh1b = Kb[base+12];
            uint32_t bl0a = Kb[base+16], bl0b = Kb[base+20];
            uint32_t bl1a = Kb[base+24], bl1b = Kb[base+28];
            #pragma unroll
            for (int mt = 0; mt < 2; ++mt) {
                float* cc = s[mt][nt];
                cc[0]=0.f; cc[1]=0.f; cc[2]=0.f; cc[3]=0.f;
                mma16816(cc, aQ[mt][0], bh0a, bh0b);
                mma16816(cc, aQ[mt][1], bh1a, bh1b);
                mma16816(cc, aQ[mt][0], bl0a, bl0b);
                mma16816(cc, aQ[mt][1], bl1a, bl1b);
                mma16816(cc, aQ[mt][2], bh0a, bh0b);
                mma16816(cc, aQ[mt][3], bh1a, bh1b);
            }
        }

        // ---- online max update ----
        float mn[2][2];
        #pragma unroll
        for (int mt = 0; mt < 2; ++mt) {
            float c0 = -1e30f, c1 = -1e30f;
            #pragma unroll
            for (int nt = 0; nt < 8; ++nt) {
                c0 = fmaxf(c0, fmaxf(s[mt][nt][0], s[mt][nt][1]));
                c1 = fmaxf(c1, fmaxf(s[mt][nt][2], s[mt][nt][3]));
            }
            c0 = fmaxf(c0, __shfl_xor_sync(0xffffffffu, c0, 1));
            c0 = fmaxf(c0, __shfl_xor_sync(0xffffffffu, c0, 2));
            c1 = fmaxf(c1, __shfl_xor_sync(0xffffffffu, c1, 1));
            c1 = fmaxf(c1, __shfl_xor_sync(0xffffffffu, c1, 2));
            mn[mt][0] = fmaxf(mrow[mt][0], c0);
            mn[mt][1] = fmaxf(mrow[mt][1], c1);
            float sc0 = ex2(mrow[mt][0] - mn[mt][0]);
            float sc1 = ex2(mrow[mt][1] - mn[mt][1]);
            mrow[mt][0] = mn[mt][0];
            mrow[mt][1] = mn[mt][1];
            #pragma unroll
            for (int nt = 0; nt < 4; ++nt) {
                oc[mt][nt][0] *= sc0; oc[mt][nt][1] *= sc0;
                oc[mt][nt][2] *= sc1; oc[mt][nt][3] *= sc1;
            }
        }

        // ---- P (bf16 hi/lo A-frags straight from S frags) + PV ----
        #pragma unroll
        for (int ks = 0; ks < 4; ++ks) {
            uint32_t aph[2][4], apl[2][4];
            #pragma unroll
            for (int mt = 0; mt < 2; ++mt) {
                float* sa = s[mt][2*ks];
                float* sb = s[mt][2*ks+1];
                float p00 = ex2(sa[0]-mn[mt][0]), p01 = ex2(sa[1]-mn[mt][0]);
                float p10 = ex2(sa[2]-mn[mt][1]), p11 = ex2(sa[3]-mn[mt][1]);
                float p20 = ex2(sb[0]-mn[mt][0]), p21 = ex2(sb[1]-mn[mt][0]);
                float p30 = ex2(sb[2]-mn[mt][1]), p31 = ex2(sb[3]-mn[mt][1]);
                uint32_t h0 = cvt2(p01, p00), h1 = cvt2(p11, p10);
                uint32_t h2 = cvt2(p21, p20), h3 = cvt2(p31, p30);
                aph[mt][0] = h0; aph[mt][1] = h1; aph[mt][2] = h2; aph[mt][3] = h3;
                apl[mt][0] = cvt2(p01 - __uint_as_float(h0 & 0xffff0000u),
                                  p00 - __uint_as_float(h0 << 16));
                apl[mt][1] = cvt2(p11 - __uint_as_float(h1 & 0xffff0000u),
                                  p10 - __uint_as_float(h1 << 16));
                apl[mt][2] = cvt2(p21 - __uint_as_float(h2 & 0xffff0000u),
                                  p20 - __uint_as_float(h2 << 16));
                apl[mt][3] = cvt2(p31 - __uint_as_float(h3 & 0xffff0000u),
                                  p30 - __uint_as_float(h3 << 16));
            }
            #pragma unroll
            for (int nt = 0; nt < 4; ++nt) {
                uint32_t base = (uint32_t)(nt*8 + qi)*36 + ks*8 + t4;
                uint32_t bh0 = Vb[base],          bh1 = Vb[base+4];
                uint32_t bl0 = Vb[base + 32*36],  bl1 = Vb[base + 32*36 + 4];
                #pragma unroll
                for (int mt = 0; mt < 2; ++mt) {
                    mma16816(oc[mt][nt], aph[mt], bh0, bh1);
                    mma16816(oc[mt][nt], apl[mt], bh0, bh1);
                    mma16816(oc[mt][nt], aph[mt], bl0, bl1);
                }
            }
        }
        __syncthreads();
    }

    // ---- write unnormalized partials (O frags + per-row max) ----
    #pragma unroll
    for (int mt = 0; mt < 2; ++mt) {
        int t_row = qtile*128 + warp*32 + mt*16 + qi;
        size_t r0 = ((size_t)kh*EBT + (size_t)eb*Tc + t_row) * Mc;
        size_t r1 = r0 + 8*Mc;
        #pragma unroll
        for (int nt = 0; nt < 4; ++nt) {
            int col = nt*8 + 2*t4;
            *(float2*)(g_pO + r0 + col) = make_float2(oc[mt][nt][0], oc[mt][nt][1]);
            *(float2*)(g_pO + r1 + col) = make_float2(oc[mt][nt][2], oc[mt][nt][3]);
        }
        if (t4 == 0) {
            g_pm[kh*EBT + eb*Tc + t_row]     = mrow[mt][0];
            g_pm[kh*EBT + eb*Tc + t_row + 8] = mrow[mt][1];
        }
    }
}

// ============================================================================
// Kernel 4: combine key-split partials + cosine epilogue. 1 thread per row.
// ============================================================================
__global__ __launch_bounds__(128)
void k_fin(float* __restrict__ out) {
    int r = blockIdx.x * 128 + threadIdx.x;   // 0 .. EBT-1
    float m0 = g_pm[r], m1 = g_pm[EBT + r], m2 = g_pm[2*EBT + r];
    float m = fmaxf(fmaxf(m0, m1), m2);
    float w0 = ex2(m0 - m), w1 = ex2(m1 - m), w2 = ex2(m2 - m);

    int eb = r >> 11, t = r & 2047;
    int e = eb / Bc, b = eb % Bc;
    int bt = b * Tc + t;

    const float4* O0 = (const float4*)(g_pO + (size_t)r * Mc);
    const float4* O1 = (const float4*)(g_pO + (size_t)(EBT + r) * Mc);
    const float4* O2 = (const float4*)(g_pO + (size_t)(2*EBT + r) * Mc);
    const float4* mem4 = (const float4*)(g_mem + (size_t)bt * Mc);
    float dot = 0.f, no2 = 0.f, nm2 = 0.f;
    #pragma unroll
    for (int i = 0; i < 8; ++i) {
        float4 a = O0[i], bb = O1[i], cc = O2[i], mm = mem4[i];
        float o0 = w0*a.x + w1*bb.x + w2*cc.x;
        float o1 = w0*a.y + w1*bb.y + w2*cc.y;
        float o2 = w0*a.z + w1*bb.z + w2*cc.z;
        float o3 = w0*a.w + w1*bb.w + w2*cc.w;
        dot += mm.x*o0 + mm.y*o1 + mm.z*o2 + mm.w*o3;
        nm2 += mm.x*mm.x + mm.y*mm.y + mm.z*mm.z + mm.w*mm.w;
        no2 += o0*o0 + o1*o1 + o2*o2 + o3*o3;
    }
    float cosv = dot / (fmaxf(sqrtf(nm2), EPSc) * fmaxf(sqrtf(no2), EPSc));
    out[(size_t)bt*Ec + e] = cosv;
}

// ============================================================================
extern "C" void kernel_launch(void* const* d_in, const int* in_sizes, int n_in,
                              void* d_out, int out_size) {
    (void)in_sizes; (void)n_in; (void)out_size;
    const float* x      = (const float*)d_in[0];
    const float* hidden = (const float*)d_in[1];
    const float* memory = (const float*)d_in[2];
    const float* Wq     = (const float*)d_in[3];
    const float* Wk     = (const float*)d_in[4];
    const float* Wv     = (const float*)d_in[5];
    const float* iq     = (const float*)d_in[6];
    float* out = (float*)d_out;

    k_mem<<<BTc/64, 256>>>(x, memory, iq);
    k_qkv<<<dim3(BTc/256, Ec), 256>>>(hidden, Wq, Wk, Wv);
    k_attn<<<dim3(QTILES*KQS, Bc, Ec), 128>>>();
    k_fin<<<EBT/128, 128>>>(out);
}